// round 2
// baseline (speedup 1.0000x reference)
#include <cuda_runtime.h>
#include <cstdint>
#include <cstddef>

// Problem constants
#define BATCH 32
#define NNODE 1024
#define FIN   128
#define HID1  64
#define HID2  32
#define OUTD  10
#define MAXDEG 96      // Binomial(1024,0.01): P(deg>96) ~ 1e-80
#define NBLK  16       // blocks per graph (64 nodes each)

typedef unsigned long long u64;

// ---------------- device scratch (no allocations allowed) ----------------
__device__ int   g_deg[BATCH * NNODE];
__device__ int   g_nbr[(size_t)BATCH * NNODE * MAXDEG];
__device__ float g_h1 [(size_t)BATCH * NNODE * HID1];
__device__ float g_bmax[BATCH * NBLK * HID2];

// ---------------- f32x2 helpers (FFMA2 only reachable via PTX) ----------------
__device__ __forceinline__ void ffma2(u64 &d, u64 a, u64 b) {
    asm("fma.rn.f32x2 %0, %1, %2, %0;" : "+l"(d) : "l"(a), "l"(b));
}
__device__ __forceinline__ void fadd2(u64 &d, u64 s) {
    asm("add.rn.f32x2 %0, %0, %1;" : "+l"(d) : "l"(s));
}
__device__ __forceinline__ u64 pack2(float lo, float hi) {
    u64 r; asm("mov.b64 %0, {%1, %2};" : "=l"(r) : "f"(lo), "f"(hi)); return r;
}
__device__ __forceinline__ float hsum2(u64 v) {
    float lo, hi; asm("mov.b64 {%0, %1}, %2;" : "=f"(lo), "=f"(hi) : "l"(v));
    return lo + hi;
}

// =====================================================================
// kernel 1: sparsify + aggregate + MLP1
// One block = 64 nodes of one graph. 256 threads.
// Dynamic smem (floats):
//   Zs  [64][132]   aggregated input (float4-aligned pitch)
//   W1p [8192]      W1a packed: [f/2][64 c][2]  (f32x2-pair friendly)
//   W2p [4096]      W2a packed: [f/2][64 c][2]
//   As  [64][68]    relu intermediate
//   msk [64]
//   sIdx[8][MAXDEG] ints
// =====================================================================
#define L1_ZS   0
#define L1_W1   (L1_ZS + 64*132)
#define L1_W2   (L1_W1 + 8192)
#define L1_AS   (L1_W2 + 4096)
#define L1_MSK  (L1_AS + 64*68)
#define L1_IDX  (L1_MSK + 64)
#define L1_FLOATS (L1_IDX + 8*MAXDEG)
#define L1_SMEM_BYTES (L1_FLOATS * 4)

__global__ void __launch_bounds__(256, 2)
gin_l1(const float* __restrict__ x, const float* __restrict__ adj,
       const float* __restrict__ mask,
       const float* __restrict__ W1a, const float* __restrict__ b1a,
       const float* __restrict__ W2a, const float* __restrict__ b2a)
{
    extern __shared__ float sm[];
    float* Zs  = sm + L1_ZS;
    float* W1p = sm + L1_W1;
    float* W2p = sm + L1_W2;
    float* As  = sm + L1_AS;
    float* msk = sm + L1_MSK;
    int*   sIdx = (int*)(sm + L1_IDX);

    const int tid   = threadIdx.x;
    const int b     = blockIdx.x >> 4;
    const int nbase = (blockIdx.x & 15) * 64;

    // stage packed weights: W1p[(f>>1)*128 + c*2 + (f&1)] = W1[f][c]
    for (int i = tid; i < 8192; i += 256) {
        int f = i >> 6, c = i & 63;
        W1p[(f >> 1)*128 + c*2 + (f & 1)] = W1a[i];
    }
    for (int i = tid; i < 4096; i += 256) {
        int f = i >> 6, c = i & 63;
        W2p[(f >> 1)*128 + c*2 + (f & 1)] = W2a[i];
    }
    if (tid < 64) msk[tid] = mask[b*NNODE + nbase + tid];

    const int w = tid >> 5;
    const int l = tid & 31;
    const unsigned lanelt = (1u << l) - 1u;
    const size_t boff = (size_t)b * NNODE;

    // ---- phase A: adj scan (ballot compaction) + pipelined gather ----
    for (int r = w; r < 64; r += 8) {
        const size_t node = boff + nbase + r;
        int* idx = sIdx + w * MAXDEG;

        ulonglong2 own = ((const ulonglong2*)(x + node * FIN))[l];
        u64 A0 = own.x, B0 = own.y;
        u64 A1 = 0, B1 = 0, A2 = 0, B2 = 0, A3 = 0, B3 = 0;

        int cnt = 0;
        const float4* arow = (const float4*)(adj + node * NNODE);
        #pragma unroll
        for (int c = 0; c < 8; ++c) {
            float4 v = __ldcs(arow + c*32 + l);   // streaming: don't pollute L2
            int base = (c*32 + l) * 4;
            unsigned mx = __ballot_sync(0xffffffffu, v.x != 0.f);
            if (v.x != 0.f) { int p = cnt + __popc(mx & lanelt); if (p < MAXDEG) idx[p] = base;   }
            cnt += __popc(mx);
            unsigned my = __ballot_sync(0xffffffffu, v.y != 0.f);
            if (v.y != 0.f) { int p = cnt + __popc(my & lanelt); if (p < MAXDEG) idx[p] = base+1; }
            cnt += __popc(my);
            unsigned mz = __ballot_sync(0xffffffffu, v.z != 0.f);
            if (v.z != 0.f) { int p = cnt + __popc(mz & lanelt); if (p < MAXDEG) idx[p] = base+2; }
            cnt += __popc(mz);
            unsigned mw = __ballot_sync(0xffffffffu, v.w != 0.f);
            if (v.w != 0.f) { int p = cnt + __popc(mw & lanelt); if (p < MAXDEG) idx[p] = base+3; }
            cnt += __popc(mw);
        }
        const int deg = min(cnt, MAXDEG);
        __syncwarp();

        // gather with 4 independent accumulator chains (MLP=4)
        int k = 0;
        for (; k + 4 <= deg; k += 4) {
            int j0 = idx[k], j1 = idx[k+1], j2 = idx[k+2], j3 = idx[k+3];
            ulonglong2 v0 = ((const ulonglong2*)(x + (boff + j0) * FIN))[l];
            ulonglong2 v1 = ((const ulonglong2*)(x + (boff + j1) * FIN))[l];
            ulonglong2 v2 = ((const ulonglong2*)(x + (boff + j2) * FIN))[l];
            ulonglong2 v3 = ((const ulonglong2*)(x + (boff + j3) * FIN))[l];
            fadd2(A0, v0.x); fadd2(B0, v0.y);
            fadd2(A1, v1.x); fadd2(B1, v1.y);
            fadd2(A2, v2.x); fadd2(B2, v2.y);
            fadd2(A3, v3.x); fadd2(B3, v3.y);
        }
        for (; k < deg; ++k) {
            int j = idx[k];
            ulonglong2 v = ((const ulonglong2*)(x + (boff + j) * FIN))[l];
            fadd2(A0, v.x); fadd2(B0, v.y);
        }
        fadd2(A0, A1); fadd2(B0, B1);
        fadd2(A2, A3); fadd2(B2, B3);
        fadd2(A0, A2); fadd2(B0, B2);

        ulonglong2 st; st.x = A0; st.y = B0;
        ((ulonglong2*)(Zs + r*132))[l] = st;

        for (int kk = l; kk < deg; kk += 32) g_nbr[node*MAXDEG + kk] = idx[kk];
        if (l == 0) g_deg[node] = deg;
        __syncwarp();
    }
    __syncthreads();

    // ---- phase B: A = relu(Z @ W1 + b1)  [64x64], f32x2 over K ----
    const int tc = tid & 15, tr = tid >> 4;
    const int n0 = tr * 4;

    u64 acc[4][4];
    #pragma unroll
    for (int cc = 0; cc < 4; ++cc) {
        u64 ini = pack2(b1a[tc + 16*cc], 0.f);
        #pragma unroll
        for (int r = 0; r < 4; ++r) acc[r][cc] = ini;
    }
    #pragma unroll 4
    for (int f = 0; f < 128; f += 2) {
        u64 z0 = *(const u64*)(Zs + (n0+0)*132 + f);
        u64 z1 = *(const u64*)(Zs + (n0+1)*132 + f);
        u64 z2 = *(const u64*)(Zs + (n0+2)*132 + f);
        u64 z3 = *(const u64*)(Zs + (n0+3)*132 + f);
        u64 w0 = *(const u64*)(W1p + f*64 + (tc     )*2);
        u64 w1 = *(const u64*)(W1p + f*64 + (tc + 16)*2);
        u64 w2 = *(const u64*)(W1p + f*64 + (tc + 32)*2);
        u64 w3 = *(const u64*)(W1p + f*64 + (tc + 48)*2);
        ffma2(acc[0][0], z0, w0); ffma2(acc[0][1], z0, w1); ffma2(acc[0][2], z0, w2); ffma2(acc[0][3], z0, w3);
        ffma2(acc[1][0], z1, w0); ffma2(acc[1][1], z1, w1); ffma2(acc[1][2], z1, w2); ffma2(acc[1][3], z1, w3);
        ffma2(acc[2][0], z2, w0); ffma2(acc[2][1], z2, w1); ffma2(acc[2][2], z2, w2); ffma2(acc[2][3], z2, w3);
        ffma2(acc[3][0], z3, w0); ffma2(acc[3][1], z3, w1); ffma2(acc[3][2], z3, w2); ffma2(acc[3][3], z3, w3);
    }
    #pragma unroll
    for (int r = 0; r < 4; ++r)
        #pragma unroll
        for (int cc = 0; cc < 4; ++cc)
            As[(n0+r)*68 + tc + 16*cc] = fmaxf(hsum2(acc[r][cc]), 0.f);
    __syncthreads();

    // ---- phase C: H1 = (A @ W2 + b2) * mask ----
    u64 acc2[4][4];
    #pragma unroll
    for (int cc = 0; cc < 4; ++cc) {
        u64 ini = pack2(b2a[tc + 16*cc], 0.f);
        #pragma unroll
        for (int r = 0; r < 4; ++r) acc2[r][cc] = ini;
    }
    #pragma unroll 4
    for (int f = 0; f < 64; f += 2) {
        u64 z0 = *(const u64*)(As + (n0+0)*68 + f);
        u64 z1 = *(const u64*)(As + (n0+1)*68 + f);
        u64 z2 = *(const u64*)(As + (n0+2)*68 + f);
        u64 z3 = *(const u64*)(As + (n0+3)*68 + f);
        u64 w0 = *(const u64*)(W2p + f*64 + (tc     )*2);
        u64 w1 = *(const u64*)(W2p + f*64 + (tc + 16)*2);
        u64 w2 = *(const u64*)(W2p + f*64 + (tc + 32)*2);
        u64 w3 = *(const u64*)(W2p + f*64 + (tc + 48)*2);
        ffma2(acc2[0][0], z0, w0); ffma2(acc2[0][1], z0, w1); ffma2(acc2[0][2], z0, w2); ffma2(acc2[0][3], z0, w3);
        ffma2(acc2[1][0], z1, w0); ffma2(acc2[1][1], z1, w1); ffma2(acc2[1][2], z1, w2); ffma2(acc2[1][3], z1, w3);
        ffma2(acc2[2][0], z2, w0); ffma2(acc2[2][1], z2, w1); ffma2(acc2[2][2], z2, w2); ffma2(acc2[2][3], z2, w3);
        ffma2(acc2[3][0], z3, w0); ffma2(acc2[3][1], z3, w1); ffma2(acc2[3][2], z3, w2); ffma2(acc2[3][3], z3, w3);
    }
    #pragma unroll
    for (int r = 0; r < 4; ++r) {
        const float m = msk[n0 + r];
        const size_t node = boff + nbase + n0 + r;
        #pragma unroll
        for (int cc = 0; cc < 4; ++cc)
            g_h1[node*HID1 + tc + 16*cc] = hsum2(acc2[r][cc]) * m;
    }
}

// =====================================================================
// kernel 2: gather(h1) + MLP2 + masked block-max (no atomics)
// =====================================================================
__global__ void __launch_bounds__(256)
gin_l2(const float* __restrict__ mask,
       const float* __restrict__ W1b, const float* __restrict__ b1b,
       const float* __restrict__ W2b, const float* __restrict__ b2b)
{
    __shared__ float Zs[64*68];   // aggregated h1
    __shared__ float W1p[2048];   // [f/2][32 c][2]
    __shared__ float W2p[1024];   // [f/2][32 c][2]
    __shared__ float As[64*36];
    __shared__ float Hs[64*33];
    __shared__ float msk[64];

    const int tid   = threadIdx.x;
    const int b     = blockIdx.x >> 4;
    const int blk   = blockIdx.x & 15;
    const int nbase = blk * 64;
    const size_t boff = (size_t)b * NNODE;

    for (int i = tid; i < 2048; i += 256) {
        int f = i >> 5, c = i & 31;
        W1p[(f >> 1)*64 + c*2 + (f & 1)] = W1b[i];
    }
    for (int i = tid; i < 1024; i += 256) {
        int f = i >> 5, c = i & 31;
        W2p[(f >> 1)*64 + c*2 + (f & 1)] = W2b[i];
    }
    if (tid < 64) msk[tid] = mask[b*NNODE + nbase + tid];

    const int w = tid >> 5;
    const int l = tid & 31;

    // ---- gather with pipelined loads ----
    for (int r = w; r < 64; r += 8) {
        const size_t node = boff + nbase + r;
        u64 a0 = *(const u64*)(g_h1 + node*HID1 + l*2);
        u64 a1 = 0, a2 = 0, a3 = 0;
        const int deg = g_deg[node];
        const int* nb = g_nbr + node*MAXDEG;
        int k = 0;
        for (; k + 4 <= deg; k += 4) {
            int j0 = nb[k], j1 = nb[k+1], j2 = nb[k+2], j3 = nb[k+3];
            u64 v0 = *(const u64*)(g_h1 + (boff + j0)*HID1 + l*2);
            u64 v1 = *(const u64*)(g_h1 + (boff + j1)*HID1 + l*2);
            u64 v2 = *(const u64*)(g_h1 + (boff + j2)*HID1 + l*2);
            u64 v3 = *(const u64*)(g_h1 + (boff + j3)*HID1 + l*2);
            fadd2(a0, v0); fadd2(a1, v1); fadd2(a2, v2); fadd2(a3, v3);
        }
        for (; k < deg; ++k) {
            u64 v = *(const u64*)(g_h1 + (boff + nb[k])*HID1 + l*2);
            fadd2(a0, v);
        }
        fadd2(a0, a1); fadd2(a2, a3); fadd2(a0, a2);
        *(u64*)(Zs + r*68 + l*2) = a0;
    }
    __syncthreads();

    // ---- MLP B: A = relu(Z @ W1b + b1b)  [64x32] ----
    const int tc = tid & 15, tr = tid >> 4;
    const int n0 = tr * 4;

    u64 acc[4][2];
    #pragma unroll
    for (int cc = 0; cc < 2; ++cc) {
        u64 ini = pack2(b1b[tc + 16*cc], 0.f);
        #pragma unroll
        for (int r = 0; r < 4; ++r) acc[r][cc] = ini;
    }
    #pragma unroll 4
    for (int f = 0; f < 64; f += 2) {
        u64 z0 = *(const u64*)(Zs + (n0+0)*68 + f);
        u64 z1 = *(const u64*)(Zs + (n0+1)*68 + f);
        u64 z2 = *(const u64*)(Zs + (n0+2)*68 + f);
        u64 z3 = *(const u64*)(Zs + (n0+3)*68 + f);
        u64 w0 = *(const u64*)(W1p + f*32 + (tc     )*2);
        u64 w1 = *(const u64*)(W1p + f*32 + (tc + 16)*2);
        ffma2(acc[0][0], z0, w0); ffma2(acc[0][1], z0, w1);
        ffma2(acc[1][0], z1, w0); ffma2(acc[1][1], z1, w1);
        ffma2(acc[2][0], z2, w0); ffma2(acc[2][1], z2, w1);
        ffma2(acc[3][0], z3, w0); ffma2(acc[3][1], z3, w1);
    }
    #pragma unroll
    for (int r = 0; r < 4; ++r)
        #pragma unroll
        for (int cc = 0; cc < 2; ++cc)
            As[(n0+r)*36 + tc + 16*cc] = fmaxf(hsum2(acc[r][cc]), 0.f);
    __syncthreads();

    // ---- MLP C: H2 = (A @ W2b + b2b) * mask ----
    u64 acc2[4][2];
    #pragma unroll
    for (int cc = 0; cc < 2; ++cc) {
        u64 ini = pack2(b2b[tc + 16*cc], 0.f);
        #pragma unroll
        for (int r = 0; r < 4; ++r) acc2[r][cc] = ini;
    }
    #pragma unroll
    for (int f = 0; f < 32; f += 2) {
        u64 z0 = *(const u64*)(As + (n0+0)*36 + f);
        u64 z1 = *(const u64*)(As + (n0+1)*36 + f);
        u64 z2 = *(const u64*)(As + (n0+2)*36 + f);
        u64 z3 = *(const u64*)(As + (n0+3)*36 + f);
        u64 w0 = *(const u64*)(W2p + f*32 + (tc     )*2);
        u64 w1 = *(const u64*)(W2p + f*32 + (tc + 16)*2);
        ffma2(acc2[0][0], z0, w0); ffma2(acc2[0][1], z0, w1);
        ffma2(acc2[1][0], z1, w0); ffma2(acc2[1][1], z1, w1);
        ffma2(acc2[2][0], z2, w0); ffma2(acc2[2][1], z2, w1);
        ffma2(acc2[3][0], z3, w0); ffma2(acc2[3][1], z3, w1);
    }
    #pragma unroll
    for (int r = 0; r < 4; ++r) {
        const float m = msk[n0 + r];
        #pragma unroll
        for (int cc = 0; cc < 2; ++cc)
            Hs[(n0+r)*33 + tc + 16*cc] = hsum2(acc2[r][cc]) * m;
    }
    __syncthreads();

    // ---- per-block max over 64 nodes, no atomics ----
    if (tid < HID2) {
        float mx = Hs[tid];
        #pragma unroll 8
        for (int n = 1; n < 64; ++n) mx = fmaxf(mx, Hs[n*33 + tid]);
        g_bmax[(b*NBLK + blk)*HID2 + tid] = mx;
    }
}

// =====================================================================
// kernel 3: reduce block maxes + FC   out = gmax @ Wfc + bfc
// =====================================================================
__global__ void gin_out(const float* __restrict__ Wfc, const float* __restrict__ bfc,
                        float* __restrict__ out)
{
    __shared__ float gm[HID2];
    const int b = blockIdx.x;
    const int t = threadIdx.x;   // 32 threads

    float mx = g_bmax[(b*NBLK)*HID2 + t];
    #pragma unroll
    for (int k = 1; k < NBLK; ++k)
        mx = fmaxf(mx, g_bmax[(b*NBLK + k)*HID2 + t]);
    gm[t] = mx;
    __syncthreads();

    if (t < OUTD) {
        float s = bfc[t];
        #pragma unroll
        for (int c = 0; c < HID2; ++c)
            s += gm[c] * Wfc[c*OUTD + t];
        out[b*OUTD + t] = s;
    }
}

// ---------------- launch ----------------
extern "C" void kernel_launch(void* const* d_in, const int* in_sizes, int n_in,
                              void* d_out, int out_size)
{
    const float* x    = (const float*)d_in[0];
    const float* adj  = (const float*)d_in[1];
    const float* mask = (const float*)d_in[2];
    const float* W1a  = (const float*)d_in[3];
    const float* b1a  = (const float*)d_in[4];
    const float* W2a  = (const float*)d_in[5];
    const float* b2a  = (const float*)d_in[6];
    const float* W1b  = (const float*)d_in[7];
    const float* b1b  = (const float*)d_in[8];
    const float* W2b  = (const float*)d_in[9];
    const float* b2b  = (const float*)d_in[10];
    const float* Wfc  = (const float*)d_in[11];
    const float* bfc  = (const float*)d_in[12];
    float* out = (float*)d_out;

    cudaFuncSetAttribute(gin_l1, cudaFuncAttributeMaxDynamicSharedMemorySize,
                         L1_SMEM_BYTES);

    gin_l1<<<BATCH*NBLK, 256, L1_SMEM_BYTES>>>(x, adj, mask, W1a, b1a, W2a, b2a);
    gin_l2<<<BATCH*NBLK, 256>>>(mask, W1b, b1b, W2b, b2b);
    gin_out<<<BATCH, HID2>>>(Wfc, bfc, out);
}

// round 3
// speedup vs baseline: 1.1548x; 1.1548x over previous
#include <cuda_runtime.h>
#include <cstdint>
#include <cstddef>

#define BATCH 32
#define NNODE 1024
#define FIN   128
#define HID1  64
#define HID2  32
#define OUTD  10
#define MAXDEG 96      // Binomial(1024,0.01): P(deg>96) ~ 1e-80
#define NBLK  16       // 64-node blocks per graph (MLP kernels)
#define SROWS 32       // rows per scan block

typedef unsigned long long u64;

// ---------------- device scratch ----------------
__device__ int   g_deg[BATCH * NNODE];
__device__ int   g_nbr[(size_t)BATCH * NNODE * MAXDEG];
__device__ float g_z  [(size_t)BATCH * NNODE * FIN];    // aggregated layer-1 input
__device__ float g_h1 [(size_t)BATCH * NNODE * HID1];
__device__ float g_bmax[BATCH * NBLK * HID2];

// ---------------- f32x2 helpers ----------------
__device__ __forceinline__ void ffma2(u64 &d, u64 a, u64 b) {
    asm("fma.rn.f32x2 %0, %1, %2, %0;" : "+l"(d) : "l"(a), "l"(b));
}
__device__ __forceinline__ void fadd2(u64 &d, u64 s) {
    asm("add.rn.f32x2 %0, %0, %1;" : "+l"(d) : "l"(s));
}
__device__ __forceinline__ u64 pack2(float lo, float hi) {
    u64 r; asm("mov.b64 %0, {%1, %2};" : "=l"(r) : "f"(lo), "f"(hi)); return r;
}
__device__ __forceinline__ float hsum2(u64 v) {
    float lo, hi; asm("mov.b64 {%0, %1}, %2;" : "=f"(lo), "=f"(hi) : "l"(v));
    return lo + hi;
}

// =====================================================================
// kernel 1: adjacency scan (block-wide rows, atomic push) + sort +
//           neighbor-sum aggregation -> g_z ; persist lists for layer 2
// grid = BATCH * (NNODE/SROWS) = 1024 blocks, 256 threads
// =====================================================================
__global__ void __launch_bounds__(256)
gin_scan(const float* __restrict__ x, const float* __restrict__ adj)
{
    __shared__ int sIdx[SROWS * MAXDEG];
    __shared__ int sCnt[SROWS];

    const int tid   = threadIdx.x;
    const int b     = blockIdx.x >> 5;           // 32 scan blocks per graph
    const int nbase = (blockIdx.x & 31) * SROWS;
    const size_t boff = (size_t)b * NNODE;

    if (tid < SROWS) sCnt[tid] = 0;
    __syncthreads();

    // ---- scan: one full row per iteration, 256 threads x float4 = 1024 cols
    const int cbase = tid * 4;
    #pragma unroll 4
    for (int r = 0; r < SROWS; ++r) {
        const size_t node = boff + nbase + r;
        float4 v = __ldcs((const float4*)(adj + node * NNODE) + tid);
        if (v.x != 0.f) { int p = atomicAdd(&sCnt[r], 1); if (p < MAXDEG) sIdx[r*MAXDEG + p] = cbase;     }
        if (v.y != 0.f) { int p = atomicAdd(&sCnt[r], 1); if (p < MAXDEG) sIdx[r*MAXDEG + p] = cbase + 1; }
        if (v.z != 0.f) { int p = atomicAdd(&sCnt[r], 1); if (p < MAXDEG) sIdx[r*MAXDEG + p] = cbase + 2; }
        if (v.w != 0.f) { int p = atomicAdd(&sCnt[r], 1); if (p < MAXDEG) sIdx[r*MAXDEG + p] = cbase + 3; }
    }
    __syncthreads();

    // ---- per-warp: sort (determinism) + gather + store ----
    const int w = tid >> 5;
    const int l = tid & 31;

    #pragma unroll
    for (int rr = 0; rr < 4; ++rr) {
        const int r = w * 4 + rr;
        const size_t node = boff + nbase + r;
        int* idx = sIdx + r * MAXDEG;
        const int deg = min(sCnt[r], MAXDEG);

        if (l == 0) {                        // insertion sort, deg ~ 10
            for (int i = 1; i < deg; ++i) {
                int key = idx[i], j = i - 1;
                while (j >= 0 && idx[j] > key) { idx[j+1] = idx[j]; --j; }
                idx[j+1] = key;
            }
        }
        __syncwarp();

        ulonglong2 own = ((const ulonglong2*)(x + node * FIN))[l];
        u64 A0 = own.x, B0 = own.y;
        u64 A1 = 0, B1 = 0, A2 = 0, B2 = 0, A3 = 0, B3 = 0;

        int k = 0;
        for (; k + 4 <= deg; k += 4) {
            int j0 = idx[k], j1 = idx[k+1], j2 = idx[k+2], j3 = idx[k+3];
            ulonglong2 v0 = ((const ulonglong2*)(x + (boff + j0) * FIN))[l];
            ulonglong2 v1 = ((const ulonglong2*)(x + (boff + j1) * FIN))[l];
            ulonglong2 v2 = ((const ulonglong2*)(x + (boff + j2) * FIN))[l];
            ulonglong2 v3 = ((const ulonglong2*)(x + (boff + j3) * FIN))[l];
            fadd2(A0, v0.x); fadd2(B0, v0.y);
            fadd2(A1, v1.x); fadd2(B1, v1.y);
            fadd2(A2, v2.x); fadd2(B2, v2.y);
            fadd2(A3, v3.x); fadd2(B3, v3.y);
        }
        for (; k < deg; ++k) {
            ulonglong2 v = ((const ulonglong2*)(x + (boff + idx[k]) * FIN))[l];
            fadd2(A0, v.x); fadd2(B0, v.y);
        }
        fadd2(A0, A1); fadd2(B0, B1);
        fadd2(A2, A3); fadd2(B2, B3);
        fadd2(A0, A2); fadd2(B0, B2);

        ulonglong2 st; st.x = A0; st.y = B0;
        ((ulonglong2*)(g_z + node * FIN))[l] = st;

        for (int kk = l; kk < deg; kk += 32) g_nbr[node*MAXDEG + kk] = idx[kk];
        if (l == 0) g_deg[node] = deg;
        __syncwarp();
    }
}

// =====================================================================
// kernel 2: MLP1  h1 = (relu(Z @ W1a + b1a) @ W2a + b2a) * mask
// grid = BATCH*NBLK (64 nodes/block), 256 threads, dynamic smem
// =====================================================================
#define L2K_ZS   0
#define L2K_W1  (L2K_ZS + 64*132)
#define L2K_W2  (L2K_W1 + 8192)
#define L2K_AS  (L2K_W2 + 4096)
#define L2K_MSK (L2K_AS + 64*68)
#define L2K_FLOATS (L2K_MSK + 64)
#define L2K_SMEM_BYTES (L2K_FLOATS * 4)

__global__ void __launch_bounds__(256, 2)
gin_mlp1(const float* __restrict__ mask,
         const float* __restrict__ W1a, const float* __restrict__ b1a,
         const float* __restrict__ W2a, const float* __restrict__ b2a)
{
    extern __shared__ float sm[];
    float* Zs  = sm + L2K_ZS;
    float* W1p = sm + L2K_W1;
    float* W2p = sm + L2K_W2;
    float* As  = sm + L2K_AS;
    float* msk = sm + L2K_MSK;

    const int tid   = threadIdx.x;
    const int b     = blockIdx.x >> 4;
    const int nbase = (blockIdx.x & 15) * 64;
    const size_t boff = (size_t)b * NNODE;

    // stage packed weights: Wp[(f>>1)*2C + c*2 + (f&1)] = W[f][c]
    for (int i = tid; i < 8192; i += 256) {
        int f = i >> 6, c = i & 63;
        W1p[(f >> 1)*128 + c*2 + (f & 1)] = W1a[i];
    }
    for (int i = tid; i < 4096; i += 256) {
        int f = i >> 6, c = i & 63;
        W2p[(f >> 1)*128 + c*2 + (f & 1)] = W2a[i];
    }
    if (tid < 64) msk[tid] = mask[b*NNODE + nbase + tid];

    // stage Z tile [64][128] -> pitch 132
    {
        const float4* src = (const float4*)(g_z + (boff + nbase) * FIN);
        for (int i = tid; i < 64*32; i += 256) {
            int row = i >> 5, q = i & 31;
            *(float4*)(Zs + row*132 + q*4) = src[i];
        }
    }
    __syncthreads();

    const int tc = tid & 15, tr = tid >> 4;
    const int n0 = tr * 4;

    // ---- A = relu(Z @ W1 + b1), f32x2 over K ----
    u64 acc[4][4];
    #pragma unroll
    for (int cc = 0; cc < 4; ++cc) {
        u64 ini = pack2(b1a[tc + 16*cc], 0.f);
        #pragma unroll
        for (int r = 0; r < 4; ++r) acc[r][cc] = ini;
    }
    #pragma unroll 4
    for (int f = 0; f < 128; f += 2) {
        u64 z0 = *(const u64*)(Zs + (n0+0)*132 + f);
        u64 z1 = *(const u64*)(Zs + (n0+1)*132 + f);
        u64 z2 = *(const u64*)(Zs + (n0+2)*132 + f);
        u64 z3 = *(const u64*)(Zs + (n0+3)*132 + f);
        u64 w0 = *(const u64*)(W1p + f*64 + (tc     )*2);
        u64 w1 = *(const u64*)(W1p + f*64 + (tc + 16)*2);
        u64 w2 = *(const u64*)(W1p + f*64 + (tc + 32)*2);
        u64 w3 = *(const u64*)(W1p + f*64 + (tc + 48)*2);
        ffma2(acc[0][0], z0, w0); ffma2(acc[0][1], z0, w1); ffma2(acc[0][2], z0, w2); ffma2(acc[0][3], z0, w3);
        ffma2(acc[1][0], z1, w0); ffma2(acc[1][1], z1, w1); ffma2(acc[1][2], z1, w2); ffma2(acc[1][3], z1, w3);
        ffma2(acc[2][0], z2, w0); ffma2(acc[2][1], z2, w1); ffma2(acc[2][2], z2, w2); ffma2(acc[2][3], z2, w3);
        ffma2(acc[3][0], z3, w0); ffma2(acc[3][1], z3, w1); ffma2(acc[3][2], z3, w2); ffma2(acc[3][3], z3, w3);
    }
    #pragma unroll
    for (int r = 0; r < 4; ++r)
        #pragma unroll
        for (int cc = 0; cc < 4; ++cc)
            As[(n0+r)*68 + tc + 16*cc] = fmaxf(hsum2(acc[r][cc]), 0.f);
    __syncthreads();

    // ---- H1 = (A @ W2 + b2) * mask ----
    u64 acc2[4][4];
    #pragma unroll
    for (int cc = 0; cc < 4; ++cc) {
        u64 ini = pack2(b2a[tc + 16*cc], 0.f);
        #pragma unroll
        for (int r = 0; r < 4; ++r) acc2[r][cc] = ini;
    }
    #pragma unroll 4
    for (int f = 0; f < 64; f += 2) {
        u64 z0 = *(const u64*)(As + (n0+0)*68 + f);
        u64 z1 = *(const u64*)(As + (n0+1)*68 + f);
        u64 z2 = *(const u64*)(As + (n0+2)*68 + f);
        u64 z3 = *(const u64*)(As + (n0+3)*68 + f);
        u64 w0 = *(const u64*)(W2p + f*64 + (tc     )*2);
        u64 w1 = *(const u64*)(W2p + f*64 + (tc + 16)*2);
        u64 w2 = *(const u64*)(W2p + f*64 + (tc + 32)*2);
        u64 w3 = *(const u64*)(W2p + f*64 + (tc + 48)*2);
        ffma2(acc2[0][0], z0, w0); ffma2(acc2[0][1], z0, w1); ffma2(acc2[0][2], z0, w2); ffma2(acc2[0][3], z0, w3);
        ffma2(acc2[1][0], z1, w0); ffma2(acc2[1][1], z1, w1); ffma2(acc2[1][2], z1, w2); ffma2(acc2[1][3], z1, w3);
        ffma2(acc2[2][0], z2, w0); ffma2(acc2[2][1], z2, w1); ffma2(acc2[2][2], z2, w2); ffma2(acc2[2][3], z2, w3);
        ffma2(acc2[3][0], z3, w0); ffma2(acc2[3][1], z3, w1); ffma2(acc2[3][2], z3, w2); ffma2(acc2[3][3], z3, w3);
    }
    #pragma unroll
    for (int r = 0; r < 4; ++r) {
        const float m = msk[n0 + r];
        const size_t node = boff + nbase + n0 + r;
        #pragma unroll
        for (int cc = 0; cc < 4; ++cc)
            g_h1[node*HID1 + tc + 16*cc] = hsum2(acc2[r][cc]) * m;
    }
}

// =====================================================================
// kernel 3: gather(h1) + MLP2 + masked block-max
// =====================================================================
__global__ void __launch_bounds__(256)
gin_l2(const float* __restrict__ mask,
       const float* __restrict__ W1b, const float* __restrict__ b1b,
       const float* __restrict__ W2b, const float* __restrict__ b2b)
{
    __shared__ float Zs[64*68];
    __shared__ float W1p[2048];
    __shared__ float W2p[1024];
    __shared__ float As[64*36];
    __shared__ float Hs[64*33];
    __shared__ float msk[64];

    const int tid   = threadIdx.x;
    const int b     = blockIdx.x >> 4;
    const int blk   = blockIdx.x & 15;
    const int nbase = blk * 64;
    const size_t boff = (size_t)b * NNODE;

    for (int i = tid; i < 2048; i += 256) {
        int f = i >> 5, c = i & 31;
        W1p[(f >> 1)*64 + c*2 + (f & 1)] = W1b[i];
    }
    for (int i = tid; i < 1024; i += 256) {
        int f = i >> 5, c = i & 31;
        W2p[(f >> 1)*64 + c*2 + (f & 1)] = W2b[i];
    }
    if (tid < 64) msk[tid] = mask[b*NNODE + nbase + tid];

    const int w = tid >> 5;
    const int l = tid & 31;

    for (int r = w; r < 64; r += 8) {
        const size_t node = boff + nbase + r;
        u64 a0 = *(const u64*)(g_h1 + node*HID1 + l*2);
        u64 a1 = 0, a2 = 0, a3 = 0;
        const int deg = g_deg[node];
        const int* nb = g_nbr + node*MAXDEG;
        int k = 0;
        for (; k + 4 <= deg; k += 4) {
            int j0 = nb[k], j1 = nb[k+1], j2 = nb[k+2], j3 = nb[k+3];
            u64 v0 = *(const u64*)(g_h1 + (boff + j0)*HID1 + l*2);
            u64 v1 = *(const u64*)(g_h1 + (boff + j1)*HID1 + l*2);
            u64 v2 = *(const u64*)(g_h1 + (boff + j2)*HID1 + l*2);
            u64 v3 = *(const u64*)(g_h1 + (boff + j3)*HID1 + l*2);
            fadd2(a0, v0); fadd2(a1, v1); fadd2(a2, v2); fadd2(a3, v3);
        }
        for (; k < deg; ++k) {
            u64 v = *(const u64*)(g_h1 + (boff + nb[k])*HID1 + l*2);
            fadd2(a0, v);
        }
        fadd2(a0, a1); fadd2(a2, a3); fadd2(a0, a2);
        *(u64*)(Zs + r*68 + l*2) = a0;
    }
    __syncthreads();

    const int tc = tid & 15, tr = tid >> 4;
    const int n0 = tr * 4;

    u64 acc[4][2];
    #pragma unroll
    for (int cc = 0; cc < 2; ++cc) {
        u64 ini = pack2(b1b[tc + 16*cc], 0.f);
        #pragma unroll
        for (int r = 0; r < 4; ++r) acc[r][cc] = ini;
    }
    #pragma unroll 4
    for (int f = 0; f < 64; f += 2) {
        u64 z0 = *(const u64*)(Zs + (n0+0)*68 + f);
        u64 z1 = *(const u64*)(Zs + (n0+1)*68 + f);
        u64 z2 = *(const u64*)(Zs + (n0+2)*68 + f);
        u64 z3 = *(const u64*)(Zs + (n0+3)*68 + f);
        u64 w0 = *(const u64*)(W1p + f*32 + (tc     )*2);
        u64 w1 = *(const u64*)(W1p + f*32 + (tc + 16)*2);
        ffma2(acc[0][0], z0, w0); ffma2(acc[0][1], z0, w1);
        ffma2(acc[1][0], z1, w0); ffma2(acc[1][1], z1, w1);
        ffma2(acc[2][0], z2, w0); ffma2(acc[2][1], z2, w1);
        ffma2(acc[3][0], z3, w0); ffma2(acc[3][1], z3, w1);
    }
    #pragma unroll
    for (int r = 0; r < 4; ++r)
        #pragma unroll
        for (int cc = 0; cc < 2; ++cc)
            As[(n0+r)*36 + tc + 16*cc] = fmaxf(hsum2(acc[r][cc]), 0.f);
    __syncthreads();

    u64 acc2[4][2];
    #pragma unroll
    for (int cc = 0; cc < 2; ++cc) {
        u64 ini = pack2(b2b[tc + 16*cc], 0.f);
        #pragma unroll
        for (int r = 0; r < 4; ++r) acc2[r][cc] = ini;
    }
    #pragma unroll
    for (int f = 0; f < 32; f += 2) {
        u64 z0 = *(const u64*)(As + (n0+0)*36 + f);
        u64 z1 = *(const u64*)(As + (n0+1)*36 + f);
        u64 z2 = *(const u64*)(As + (n0+2)*36 + f);
        u64 z3 = *(const u64*)(As + (n0+3)*36 + f);
        u64 w0 = *(const u64*)(W2p + f*32 + (tc     )*2);
        u64 w1 = *(const u64*)(W2p + f*32 + (tc + 16)*2);
        ffma2(acc2[0][0], z0, w0); ffma2(acc2[0][1], z0, w1);
        ffma2(acc2[1][0], z1, w0); ffma2(acc2[1][1], z1, w1);
        ffma2(acc2[2][0], z2, w0); ffma2(acc2[2][1], z2, w1);
        ffma2(acc2[3][0], z3, w0); ffma2(acc2[3][1], z3, w1);
    }
    #pragma unroll
    for (int r = 0; r < 4; ++r) {
        const float m = msk[n0 + r];
        #pragma unroll
        for (int cc = 0; cc < 2; ++cc)
            Hs[(n0+r)*33 + tc + 16*cc] = hsum2(acc2[r][cc]) * m;
    }
    __syncthreads();

    if (tid < HID2) {
        float mx = Hs[tid];
        #pragma unroll 8
        for (int n = 1; n < 64; ++n) mx = fmaxf(mx, Hs[n*33 + tid]);
        g_bmax[(b*NBLK + blk)*HID2 + tid] = mx;
    }
}

// =====================================================================
// kernel 4: reduce block maxes + FC
// =====================================================================
__global__ void gin_out(const float* __restrict__ Wfc, const float* __restrict__ bfc,
                        float* __restrict__ out)
{
    __shared__ float gm[HID2];
    const int b = blockIdx.x;
    const int t = threadIdx.x;

    float mx = g_bmax[(b*NBLK)*HID2 + t];
    #pragma unroll
    for (int k = 1; k < NBLK; ++k)
        mx = fmaxf(mx, g_bmax[(b*NBLK + k)*HID2 + t]);
    gm[t] = mx;
    __syncthreads();

    if (t < OUTD) {
        float s = bfc[t];
        #pragma unroll
        for (int c = 0; c < HID2; ++c)
            s += gm[c] * Wfc[c*OUTD + t];
        out[b*OUTD + t] = s;
    }
}

// ---------------- launch ----------------
extern "C" void kernel_launch(void* const* d_in, const int* in_sizes, int n_in,
                              void* d_out, int out_size)
{
    const float* x    = (const float*)d_in[0];
    const float* adj  = (const float*)d_in[1];
    const float* mask = (const float*)d_in[2];
    const float* W1a  = (const float*)d_in[3];
    const float* b1a  = (const float*)d_in[4];
    const float* W2a  = (const float*)d_in[5];
    const float* b2a  = (const float*)d_in[6];
    const float* W1b  = (const float*)d_in[7];
    const float* b1b  = (const float*)d_in[8];
    const float* W2b  = (const float*)d_in[9];
    const float* b2b  = (const float*)d_in[10];
    const float* Wfc  = (const float*)d_in[11];
    const float* bfc  = (const float*)d_in[12];
    float* out = (float*)d_out;

    cudaFuncSetAttribute(gin_mlp1, cudaFuncAttributeMaxDynamicSharedMemorySize,
                         L2K_SMEM_BYTES);

    gin_scan<<<BATCH*(NNODE/SROWS), 256>>>(x, adj);
    gin_mlp1<<<BATCH*NBLK, 256, L2K_SMEM_BYTES>>>(mask, W1a, b1a, W2a, b2a);
    gin_l2<<<BATCH*NBLK, 256>>>(mask, W1b, b1b, W2b, b2b);
    gin_out<<<BATCH, HID2>>>(Wfc, bfc, out);
}

// round 4
// speedup vs baseline: 1.2285x; 1.0638x over previous
#include <cuda_runtime.h>
#include <cstdint>
#include <cstddef>

#define BATCH 32
#define NNODE 1024
#define FIN   128
#define HID1  64
#define HID2  32
#define OUTD  10
#define MAXDEG 96      // Binomial(1024,0.01): P(deg>96) ~ 1e-80
#define NBLK  16       // 64-node blocks per graph
#define SROWS 32       // rows per scan block

typedef unsigned long long u64;

// ---------------- device scratch ----------------
__device__ int   g_deg[BATCH * NNODE];
__device__ int   g_nbr[(size_t)BATCH * NNODE * MAXDEG];
__device__ float g_y1 [(size_t)BATCH * NNODE * HID1];   // x @ W1a
__device__ float g_y2 [(size_t)BATCH * NNODE * HID2];   // h1 @ W1b
__device__ float g_bmax[BATCH * NBLK * HID2];

// ---------------- f32x2 helpers ----------------
__device__ __forceinline__ void ffma2(u64 &d, u64 a, u64 b) {
    asm("fma.rn.f32x2 %0, %1, %2, %0;" : "+l"(d) : "l"(a), "l"(b));
}
__device__ __forceinline__ void fadd2(u64 &d, u64 s) {
    asm("add.rn.f32x2 %0, %0, %1;" : "+l"(d) : "l"(s));
}
__device__ __forceinline__ u64 pack2(float lo, float hi) {
    u64 r; asm("mov.b64 %0, {%1, %2};" : "=l"(r) : "f"(lo), "f"(hi)); return r;
}
__device__ __forceinline__ void unpack2(u64 v, float &lo, float &hi) {
    asm("mov.b64 {%0, %1}, %2;" : "=f"(lo), "=f"(hi) : "l"(v));
}
__device__ __forceinline__ float hsum2(u64 v) {
    float lo, hi; unpack2(v, lo, hi); return lo + hi;
}

// =====================================================================
// K1: pure adjacency scan -> neighbor lists (sorted). BW-bound.
// grid = BATCH*32, 256 threads.
// =====================================================================
__global__ void __launch_bounds__(256)
gin_scan(const float* __restrict__ adj)
{
    __shared__ int sIdx[SROWS * MAXDEG];
    __shared__ int sCnt[SROWS];

    const int tid   = threadIdx.x;
    const int b     = blockIdx.x >> 5;
    const int nbase = (blockIdx.x & 31) * SROWS;
    const size_t boff = (size_t)b * NNODE;

    if (tid < SROWS) sCnt[tid] = 0;
    __syncthreads();

    const int cbase = tid * 4;
    #pragma unroll 4
    for (int r = 0; r < SROWS; ++r) {
        const size_t node = boff + nbase + r;
        uint4 v = __ldcs((const uint4*)(adj + node * NNODE) + tid);
        if (v.x | v.y | v.z | v.w) {          // rare (~4% of threads)
            if (v.x) { int p = atomicAdd(&sCnt[r], 1); if (p < MAXDEG) sIdx[r*MAXDEG + p] = cbase;     }
            if (v.y) { int p = atomicAdd(&sCnt[r], 1); if (p < MAXDEG) sIdx[r*MAXDEG + p] = cbase + 1; }
            if (v.z) { int p = atomicAdd(&sCnt[r], 1); if (p < MAXDEG) sIdx[r*MAXDEG + p] = cbase + 2; }
            if (v.w) { int p = atomicAdd(&sCnt[r], 1); if (p < MAXDEG) sIdx[r*MAXDEG + p] = cbase + 3; }
        }
    }
    __syncthreads();

    const int w = tid >> 5;
    const int l = tid & 31;
    #pragma unroll
    for (int rr = 0; rr < 4; ++rr) {
        const int r = w * 4 + rr;
        const size_t node = boff + nbase + r;
        int* idx = sIdx + r * MAXDEG;
        const int deg = min(sCnt[r], MAXDEG);
        if (l == 0) {                         // insertion sort (deg ~ 10), determinism
            for (int i = 1; i < deg; ++i) {
                int key = idx[i], j = i - 1;
                while (j >= 0 && idx[j] > key) { idx[j+1] = idx[j]; --j; }
                idx[j+1] = key;
            }
        }
        __syncwarp();
        for (int kk = l; kk < deg; kk += 32) g_nbr[node*MAXDEG + kk] = idx[kk];
        if (l == 0) g_deg[node] = deg;
        __syncwarp();
    }
}

// =====================================================================
// K2: Y1 = x @ W1a    (32768 x 128 x 64), float4-quad FFMA2 GEMM
// grid = 512 (64 rows/block), 256 threads. dyn smem.
// =====================================================================
#define K2_XS   0                    // 64*132
#define K2_W    (64*132)             // 8192 (quad-packed)
#define K2_FLOATS (K2_W + 8192)
#define K2_SMEM  (K2_FLOATS * 4)

__global__ void __launch_bounds__(256, 2)
gin_ygemm(const float* __restrict__ x, const float* __restrict__ W1a)
{
    extern __shared__ float sm[];
    float* Xs = sm + K2_XS;
    float* Wq = sm + K2_W;

    const int tid = threadIdx.x;
    const int m0  = blockIdx.x * 64;

    // quad-pack W1a [128][64]: Wq[(f>>2)*256 + c*4 + (f&3)]
    for (int i = tid; i < 8192; i += 256) {
        int f = i >> 6, c = i & 63;
        Wq[(f >> 2)*256 + c*4 + (f & 3)] = W1a[i];
    }
    // stage x tile [64][128] -> pitch 132
    {
        const float4* src = (const float4*)(x + (size_t)m0 * FIN);
        for (int i = tid; i < 64*32; i += 256) {
            int row = i >> 5, q = i & 31;
            *(float4*)(Xs + row*132 + q*4) = src[i];
        }
    }
    __syncthreads();

    const int tc = tid & 15, tr = tid >> 4;
    const int n0 = tr * 4;

    u64 acc[4][4];
    #pragma unroll
    for (int r = 0; r < 4; ++r)
        #pragma unroll
        for (int cc = 0; cc < 4; ++cc) acc[r][cc] = 0;

    #pragma unroll 2
    for (int f = 0; f < 128; f += 4) {
        ulonglong2 z0 = *(const ulonglong2*)(Xs + (n0+0)*132 + f);
        ulonglong2 z1 = *(const ulonglong2*)(Xs + (n0+1)*132 + f);
        ulonglong2 z2 = *(const ulonglong2*)(Xs + (n0+2)*132 + f);
        ulonglong2 z3 = *(const ulonglong2*)(Xs + (n0+3)*132 + f);
        const float* wb = Wq + (f >> 2)*256;
        ulonglong2 w0 = *(const ulonglong2*)(wb + (tc     )*4);
        ulonglong2 w1 = *(const ulonglong2*)(wb + (tc + 16)*4);
        ulonglong2 w2 = *(const ulonglong2*)(wb + (tc + 32)*4);
        ulonglong2 w3 = *(const ulonglong2*)(wb + (tc + 48)*4);
        ffma2(acc[0][0], z0.x, w0.x); ffma2(acc[0][0], z0.y, w0.y);
        ffma2(acc[0][1], z0.x, w1.x); ffma2(acc[0][1], z0.y, w1.y);
        ffma2(acc[0][2], z0.x, w2.x); ffma2(acc[0][2], z0.y, w2.y);
        ffma2(acc[0][3], z0.x, w3.x); ffma2(acc[0][3], z0.y, w3.y);
        ffma2(acc[1][0], z1.x, w0.x); ffma2(acc[1][0], z1.y, w0.y);
        ffma2(acc[1][1], z1.x, w1.x); ffma2(acc[1][1], z1.y, w1.y);
        ffma2(acc[1][2], z1.x, w2.x); ffma2(acc[1][2], z1.y, w2.y);
        ffma2(acc[1][3], z1.x, w3.x); ffma2(acc[1][3], z1.y, w3.y);
        ffma2(acc[2][0], z2.x, w0.x); ffma2(acc[2][0], z2.y, w0.y);
        ffma2(acc[2][1], z2.x, w1.x); ffma2(acc[2][1], z2.y, w1.y);
        ffma2(acc[2][2], z2.x, w2.x); ffma2(acc[2][2], z2.y, w2.y);
        ffma2(acc[2][3], z2.x, w3.x); ffma2(acc[2][3], z2.y, w3.y);
        ffma2(acc[3][0], z3.x, w0.x); ffma2(acc[3][0], z3.y, w0.y);
        ffma2(acc[3][1], z3.x, w1.x); ffma2(acc[3][1], z3.y, w1.y);
        ffma2(acc[3][2], z3.x, w2.x); ffma2(acc[3][2], z3.y, w2.y);
        ffma2(acc[3][3], z3.x, w3.x); ffma2(acc[3][3], z3.y, w3.y);
    }
    #pragma unroll
    for (int r = 0; r < 4; ++r)
        #pragma unroll
        for (int cc = 0; cc < 4; ++cc)
            g_y1[(size_t)(m0 + n0 + r)*HID1 + tc + 16*cc] = hsum2(acc[r][cc]);
}

// =====================================================================
// K3: Zy=gather(Y1); A=relu(Zy+b1a); H1=(A@W2a+b2a)*mask; Y2=H1@W1b
// grid = BATCH*NBLK, 256 threads. dyn smem.
// =====================================================================
#define K3_ZS   0                     // 64*68 (A after relu)
#define K3_W2   (K3_ZS + 64*68)       // 4096 quad-packed W2a
#define K3_W1B  (K3_W2 + 4096)        // 2048 quad-packed W1b
#define K3_HS   (K3_W1B + 2048)       // 64*68 H1
#define K3_MSK  (K3_HS + 64*68)
#define K3_FLOATS (K3_MSK + 64)
#define K3_SMEM  (K3_FLOATS * 4)

__global__ void __launch_bounds__(256, 2)
gin_layer1b(const float* __restrict__ mask,
            const float* __restrict__ b1a,
            const float* __restrict__ W2a, const float* __restrict__ b2a,
            const float* __restrict__ W1b)
{
    extern __shared__ float sm[];
    float* Zs  = sm + K3_ZS;
    float* W2q = sm + K3_W2;
    float* W1q = sm + K3_W1B;
    float* Hs  = sm + K3_HS;
    float* msk = sm + K3_MSK;

    const int tid   = threadIdx.x;
    const int b     = blockIdx.x >> 4;
    const int nbase = (blockIdx.x & 15) * 64;
    const size_t boff = (size_t)b * NNODE;

    for (int i = tid; i < 4096; i += 256) {
        int f = i >> 6, c = i & 63;
        W2q[(f >> 2)*256 + c*4 + (f & 3)] = W2a[i];
    }
    for (int i = tid; i < 2048; i += 256) {
        int f = i >> 5, c = i & 31;
        W1q[(f >> 2)*128 + c*4 + (f & 3)] = W1b[i];
    }
    if (tid < 64) msk[tid] = mask[b*NNODE + nbase + tid];

    const int w = tid >> 5;
    const int l = tid & 31;

    // gather Y1 (64-dim rows, 256B), bias+relu, -> Zs
    const float blo = b1a[2*l], bhi = b1a[2*l + 1];
    for (int r = w; r < 64; r += 8) {
        const size_t node = boff + nbase + r;
        u64 a0 = *(const u64*)(g_y1 + node*HID1 + 2*l);
        u64 a1 = 0, a2 = 0, a3 = 0;
        const int deg = g_deg[node];
        const int* nb = g_nbr + node*MAXDEG;
        int k = 0;
        for (; k + 4 <= deg; k += 4) {
            int j0 = nb[k], j1 = nb[k+1], j2 = nb[k+2], j3 = nb[k+3];
            u64 v0 = *(const u64*)(g_y1 + (boff + j0)*HID1 + 2*l);
            u64 v1 = *(const u64*)(g_y1 + (boff + j1)*HID1 + 2*l);
            u64 v2 = *(const u64*)(g_y1 + (boff + j2)*HID1 + 2*l);
            u64 v3 = *(const u64*)(g_y1 + (boff + j3)*HID1 + 2*l);
            fadd2(a0, v0); fadd2(a1, v1); fadd2(a2, v2); fadd2(a3, v3);
        }
        for (; k < deg; ++k)
            fadd2(a0, *(const u64*)(g_y1 + (boff + nb[k])*HID1 + 2*l));
        fadd2(a0, a1); fadd2(a2, a3); fadd2(a0, a2);
        float lo, hi; unpack2(a0, lo, hi);
        lo = fmaxf(lo + blo, 0.f); hi = fmaxf(hi + bhi, 0.f);
        *(u64*)(Zs + r*68 + 2*l) = pack2(lo, hi);
    }
    __syncthreads();

    const int tc = tid & 15, tr = tid >> 4;
    const int n0 = tr * 4;

    // GEMM1: H1 = (A @ W2a + b2a) * mask  [64x64, K=64]
    u64 acc[4][4];
    #pragma unroll
    for (int cc = 0; cc < 4; ++cc) {
        u64 ini = pack2(b2a[tc + 16*cc], 0.f);
        #pragma unroll
        for (int r = 0; r < 4; ++r) acc[r][cc] = ini;
    }
    #pragma unroll 2
    for (int f = 0; f < 64; f += 4) {
        ulonglong2 z0 = *(const ulonglong2*)(Zs + (n0+0)*68 + f);
        ulonglong2 z1 = *(const ulonglong2*)(Zs + (n0+1)*68 + f);
        ulonglong2 z2 = *(const ulonglong2*)(Zs + (n0+2)*68 + f);
        ulonglong2 z3 = *(const ulonglong2*)(Zs + (n0+3)*68 + f);
        const float* wb = W2q + (f >> 2)*256;
        ulonglong2 w0 = *(const ulonglong2*)(wb + (tc     )*4);
        ulonglong2 w1 = *(const ulonglong2*)(wb + (tc + 16)*4);
        ulonglong2 w2 = *(const ulonglong2*)(wb + (tc + 32)*4);
        ulonglong2 w3 = *(const ulonglong2*)(wb + (tc + 48)*4);
        ffma2(acc[0][0], z0.x, w0.x); ffma2(acc[0][0], z0.y, w0.y);
        ffma2(acc[0][1], z0.x, w1.x); ffma2(acc[0][1], z0.y, w1.y);
        ffma2(acc[0][2], z0.x, w2.x); ffma2(acc[0][2], z0.y, w2.y);
        ffma2(acc[0][3], z0.x, w3.x); ffma2(acc[0][3], z0.y, w3.y);
        ffma2(acc[1][0], z1.x, w0.x); ffma2(acc[1][0], z1.y, w0.y);
        ffma2(acc[1][1], z1.x, w1.x); ffma2(acc[1][1], z1.y, w1.y);
        ffma2(acc[1][2], z1.x, w2.x); ffma2(acc[1][2], z1.y, w2.y);
        ffma2(acc[1][3], z1.x, w3.x); ffma2(acc[1][3], z1.y, w3.y);
        ffma2(acc[2][0], z2.x, w0.x); ffma2(acc[2][0], z2.y, w0.y);
        ffma2(acc[2][1], z2.x, w1.x); ffma2(acc[2][1], z2.y, w1.y);
        ffma2(acc[2][2], z2.x, w2.x); ffma2(acc[2][2], z2.y, w2.y);
        ffma2(acc[2][3], z2.x, w3.x); ffma2(acc[2][3], z2.y, w3.y);
        ffma2(acc[3][0], z3.x, w0.x); ffma2(acc[3][0], z3.y, w0.y);
        ffma2(acc[3][1], z3.x, w1.x); ffma2(acc[3][1], z3.y, w1.y);
        ffma2(acc[3][2], z3.x, w2.x); ffma2(acc[3][2], z3.y, w2.y);
        ffma2(acc[3][3], z3.x, w3.x); ffma2(acc[3][3], z3.y, w3.y);
    }
    #pragma unroll
    for (int r = 0; r < 4; ++r) {
        const float m = msk[n0 + r];
        #pragma unroll
        for (int cc = 0; cc < 4; ++cc)
            Hs[(n0+r)*68 + tc + 16*cc] = hsum2(acc[r][cc]) * m;
    }
    __syncthreads();

    // GEMM2: Y2 = H1 @ W1b  [64x32, K=64]  (no bias: added post-aggregation)
    u64 acc3[4][2];
    #pragma unroll
    for (int r = 0; r < 4; ++r) { acc3[r][0] = 0; acc3[r][1] = 0; }
    #pragma unroll 2
    for (int f = 0; f < 64; f += 4) {
        ulonglong2 z0 = *(const ulonglong2*)(Hs + (n0+0)*68 + f);
        ulonglong2 z1 = *(const ulonglong2*)(Hs + (n0+1)*68 + f);
        ulonglong2 z2 = *(const ulonglong2*)(Hs + (n0+2)*68 + f);
        ulonglong2 z3 = *(const ulonglong2*)(Hs + (n0+3)*68 + f);
        const float* wb = W1q + (f >> 2)*128;
        ulonglong2 w0 = *(const ulonglong2*)(wb + (tc     )*4);
        ulonglong2 w1 = *(const ulonglong2*)(wb + (tc + 16)*4);
        ffma2(acc3[0][0], z0.x, w0.x); ffma2(acc3[0][0], z0.y, w0.y);
        ffma2(acc3[0][1], z0.x, w1.x); ffma2(acc3[0][1], z0.y, w1.y);
        ffma2(acc3[1][0], z1.x, w0.x); ffma2(acc3[1][0], z1.y, w0.y);
        ffma2(acc3[1][1], z1.x, w1.x); ffma2(acc3[1][1], z1.y, w1.y);
        ffma2(acc3[2][0], z2.x, w0.x); ffma2(acc3[2][0], z2.y, w0.y);
        ffma2(acc3[2][1], z2.x, w1.x); ffma2(acc3[2][1], z2.y, w1.y);
        ffma2(acc3[3][0], z3.x, w0.x); ffma2(acc3[3][0], z3.y, w0.y);
        ffma2(acc3[3][1], z3.x, w1.x); ffma2(acc3[3][1], z3.y, w1.y);
    }
    #pragma unroll
    for (int r = 0; r < 4; ++r) {
        const size_t node = boff + nbase + n0 + r;
        g_y2[node*HID2 + tc     ] = hsum2(acc3[r][0]);
        g_y2[node*HID2 + tc + 16] = hsum2(acc3[r][1]);
    }
}

// =====================================================================
// K4: Zy2=gather(Y2); A=relu(Zy2+b1b); H2=(A@W2b+b2b)*mask; blockmax
// grid = BATCH*NBLK, 256 threads, static smem.
// =====================================================================
__global__ void __launch_bounds__(256)
gin_layer2(const float* __restrict__ mask,
           const float* __restrict__ b1b,
           const float* __restrict__ W2b, const float* __restrict__ b2b)
{
    __shared__ float Zs[64*36];
    __shared__ float W2q[1024];
    __shared__ float Hs[64*33];
    __shared__ float msk[64];

    const int tid   = threadIdx.x;
    const int b     = blockIdx.x >> 4;
    const int blk   = blockIdx.x & 15;
    const int nbase = blk * 64;
    const size_t boff = (size_t)b * NNODE;

    for (int i = tid; i < 1024; i += 256) {
        int f = i >> 5, c = i & 31;
        W2q[(f >> 2)*128 + c*4 + (f & 3)] = W2b[i];
    }
    if (tid < 64) msk[tid] = mask[b*NNODE + nbase + tid];

    const int w = tid >> 5;
    const int l = tid & 31;
    const float bl = b1b[l];

    // gather Y2 (32-dim rows = 128B), bias+relu
    for (int r = w; r < 64; r += 8) {
        const size_t node = boff + nbase + r;
        float a0 = g_y2[node*HID2 + l];
        float a1 = 0.f, a2 = 0.f, a3 = 0.f;
        const int deg = g_deg[node];
        const int* nb = g_nbr + node*MAXDEG;
        int k = 0;
        for (; k + 4 <= deg; k += 4) {
            int j0 = nb[k], j1 = nb[k+1], j2 = nb[k+2], j3 = nb[k+3];
            a0 += g_y2[(boff + j0)*HID2 + l];
            a1 += g_y2[(boff + j1)*HID2 + l];
            a2 += g_y2[(boff + j2)*HID2 + l];
            a3 += g_y2[(boff + j3)*HID2 + l];
        }
        for (; k < deg; ++k) a0 += g_y2[(boff + nb[k])*HID2 + l];
        a0 = ((a0 + a1) + (a2 + a3));
        Zs[r*36 + l] = fmaxf(a0 + bl, 0.f);
    }
    __syncthreads();

    const int tc = tid & 15, tr = tid >> 4;
    const int n0 = tr * 4;

    u64 acc[4][2];
    #pragma unroll
    for (int cc = 0; cc < 2; ++cc) {
        u64 ini = pack2(b2b[tc + 16*cc], 0.f);
        #pragma unroll
        for (int r = 0; r < 4; ++r) acc[r][cc] = ini;
    }
    #pragma unroll
    for (int f = 0; f < 32; f += 4) {
        ulonglong2 z0 = *(const ulonglong2*)(Zs + (n0+0)*36 + f);
        ulonglong2 z1 = *(const ulonglong2*)(Zs + (n0+1)*36 + f);
        ulonglong2 z2 = *(const ulonglong2*)(Zs + (n0+2)*36 + f);
        ulonglong2 z3 = *(const ulonglong2*)(Zs + (n0+3)*36 + f);
        const float* wb = W2q + (f >> 2)*128;
        ulonglong2 w0 = *(const ulonglong2*)(wb + (tc     )*4);
        ulonglong2 w1 = *(const ulonglong2*)(wb + (tc + 16)*4);
        ffma2(acc[0][0], z0.x, w0.x); ffma2(acc[0][0], z0.y, w0.y);
        ffma2(acc[0][1], z0.x, w1.x); ffma2(acc[0][1], z0.y, w1.y);
        ffma2(acc[1][0], z1.x, w0.x); ffma2(acc[1][0], z1.y, w0.y);
        ffma2(acc[1][1], z1.x, w1.x); ffma2(acc[1][1], z1.y, w1.y);
        ffma2(acc[2][0], z2.x, w0.x); ffma2(acc[2][0], z2.y, w0.y);
        ffma2(acc[2][1], z2.x, w1.x); ffma2(acc[2][1], z2.y, w1.y);
        ffma2(acc[3][0], z3.x, w0.x); ffma2(acc[3][0], z3.y, w0.y);
        ffma2(acc[3][1], z3.x, w1.x); ffma2(acc[3][1], z3.y, w1.y);
    }
    #pragma unroll
    for (int r = 0; r < 4; ++r) {
        const float m = msk[n0 + r];
        Hs[(n0+r)*33 + tc     ] = hsum2(acc[r][0]) * m;
        Hs[(n0+r)*33 + tc + 16] = hsum2(acc[r][1]) * m;
    }
    __syncthreads();

    if (tid < HID2) {
        float mx = Hs[tid];
        #pragma unroll 8
        for (int n = 1; n < 64; ++n) mx = fmaxf(mx, Hs[n*33 + tid]);
        g_bmax[(b*NBLK + blk)*HID2 + tid] = mx;
    }
}

// =====================================================================
// K5: reduce block maxes + FC
// =====================================================================
__global__ void gin_out(const float* __restrict__ Wfc, const float* __restrict__ bfc,
                        float* __restrict__ out)
{
    __shared__ float gm[HID2];
    const int b = blockIdx.x;
    const int t = threadIdx.x;

    float mx = g_bmax[(b*NBLK)*HID2 + t];
    #pragma unroll
    for (int k = 1; k < NBLK; ++k)
        mx = fmaxf(mx, g_bmax[(b*NBLK + k)*HID2 + t]);
    gm[t] = mx;
    __syncthreads();

    if (t < OUTD) {
        float s = bfc[t];
        #pragma unroll
        for (int c = 0; c < HID2; ++c)
            s += gm[c] * Wfc[c*OUTD + t];
        out[b*OUTD + t] = s;
    }
}

// ---------------- launch ----------------
extern "C" void kernel_launch(void* const* d_in, const int* in_sizes, int n_in,
                              void* d_out, int out_size)
{
    const float* x    = (const float*)d_in[0];
    const float* adj  = (const float*)d_in[1];
    const float* mask = (const float*)d_in[2];
    const float* W1a  = (const float*)d_in[3];
    const float* b1a  = (const float*)d_in[4];
    const float* W2a  = (const float*)d_in[5];
    const float* b2a  = (const float*)d_in[6];
    const float* W1b  = (const float*)d_in[7];
    const float* b1b  = (const float*)d_in[8];
    const float* W2b  = (const float*)d_in[9];
    const float* b2b  = (const float*)d_in[10];
    const float* Wfc  = (const float*)d_in[11];
    const float* bfc  = (const float*)d_in[12];
    float* out = (float*)d_out;

    cudaFuncSetAttribute(gin_ygemm,  cudaFuncAttributeMaxDynamicSharedMemorySize, K2_SMEM);
    cudaFuncSetAttribute(gin_layer1b, cudaFuncAttributeMaxDynamicSharedMemorySize, K3_SMEM);

    gin_scan<<<BATCH*(NNODE/SROWS), 256>>>(adj);
    gin_ygemm<<<(BATCH*NNODE)/64, 256, K2_SMEM>>>(x, W1a);
    gin_layer1b<<<BATCH*NBLK, 256, K3_SMEM>>>(mask, b1a, W2a, b2a, W1b);
    gin_layer2<<<BATCH*NBLK, 256>>>(mask, b1b, W2b, b2b);
    gin_out<<<BATCH, HID2>>>(Wfc, bfc, out);
}